// round 7
// baseline (speedup 1.0000x reference)
#include <cuda_runtime.h>
#include <cuda_bf16.h>

// Problem constants
#define NGROUPS 8
#define CIN 4
#define COUT 4
#define KSIZE 5
#define NPART 8
#define B_    8
#define H_    256
#define W_    512
#define CI_   32
#define CO_   32
#define HP_   32      // H_/NPART rows per slab

// Tile config: 64 cols x 4 rows x 32 co per block.
// Thread = (xsub: 8 cols) x (co-pair: 2 co) x (band: 2 rows) -> 8*16*2 = 256
#define TX 64
#define TY 4
#define XS 8
#define NTHREADS 256

#define SIN_ROWS 6            // TY + 2
#define SIN_COLS 68           // TX + 4
#define SIN_ELEMS (CI_ * SIN_ROWS * SIN_COLS)       // 13056
#define SMEM_BYTES (SIN_ELEMS * 4)                  // 52224 -> 4 blocks/SM

// Masked weights in global, grouped+padded layout [ci][co][24]:
//   slots 0..4   : ky=0 taps kx 0..4
//   slots 8..12  : ky=1 taps kx 0..4
//   slots 16..18 : ky=2 taps kx 0..2 (kx2 = group-gated center)
// All group starts are 16B-aligned -> each group = LDG.128 (+ LDG.32).
#define WROW 24
__device__ float g_w[CI_ * CO_ * WROW];

// ---------------------------------------------------------------------------
// Prep: apply PixelCNN group mask (HIDDEN: center visible iff gin<=gout)
// ---------------------------------------------------------------------------
__global__ void prep_weights(const float* __restrict__ w) {
    int i = blockIdx.x * blockDim.x + threadIdx.x;
    if (i >= CI_ * CO_ * WROW) return;
    int slot = i % WROW;
    int co   = (i / WROW) & 31;
    int ci   = i / (WROW * CO_);
    float val = 0.0f;
    int ky = -1, kx = 0;
    if (slot < 5)                      { ky = 0; kx = slot; }
    else if (slot >= 8 && slot < 13)   { ky = 1; kx = slot - 8; }
    else if (slot >= 16 && slot < 19)  { ky = 2; kx = slot - 16; }
    if (ky >= 0) {
        float m = 1.0f;
        if (ky == 2 && kx == 2)
            m = ((ci >> 2) <= (co >> 2)) ? 1.0f : 0.0f;
        val = w[((co * CI_ + ci) * KSIZE + ky) * KSIZE + kx] * m;
    }
    g_w[i] = val;
}

// ---------------------------------------------------------------------------
// Device helpers
// ---------------------------------------------------------------------------
__device__ __forceinline__ void load_g5(float* wA, float* wB,
                                        const float* __restrict__ wp, int off) {
    float4 qa = __ldg((const float4*)(wp + off));
    wA[0]=qa.x; wA[1]=qa.y; wA[2]=qa.z; wA[3]=qa.w;
    wA[4]=__ldg(wp + off + 4);
    float4 qb = __ldg((const float4*)(wp + WROW + off));
    wB[0]=qb.x; wB[1]=qb.y; wB[2]=qb.z; wB[3]=qb.w;
    wB[4]=__ldg(wp + WROW + off + 4);
}

__device__ __forceinline__ void load_g3(float* wA, float* wB,
                                        const float* __restrict__ wp) {
    float4 qa = __ldg((const float4*)(wp + 16));
    wA[0]=qa.x; wA[1]=qa.y; wA[2]=qa.z;
    float4 qb = __ldg((const float4*)(wp + WROW + 16));
    wB[0]=qb.x; wB[1]=qb.y; wB[2]=qb.z;
}

__device__ __forceinline__ void load_v(float* v, const float* __restrict__ rb) {
    const float4 a0 = *(const float4*)(rb);
    const float4 a1 = *(const float4*)(rb + 4);
    const float4 a2 = *(const float4*)(rb + 8);
    v[0]=a0.x; v[1]=a0.y; v[2]=a0.z; v[3]=a0.w;
    v[4]=a1.x; v[5]=a1.y; v[6]=a1.z; v[7]=a1.w;
    v[8]=a2.x; v[9]=a2.y; v[10]=a2.z; v[11]=a2.w;
}

// accA/accB: 8-wide accumulators for co0/co1
__device__ __forceinline__ void fma5(float* accA, float* accB,
                                     const float* v, const float* wA,
                                     const float* wB) {
    #pragma unroll
    for (int kx = 0; kx < 5; ++kx)
        #pragma unroll
        for (int j = 0; j < XS; ++j) {
            accA[j] = fmaf(v[j + kx], wA[kx], accA[j]);
            accB[j] = fmaf(v[j + kx], wB[kx], accB[j]);
        }
}

__device__ __forceinline__ void fma3(float* accA, float* accB,
                                     const float* v, const float* wA,
                                     const float* wB) {
    #pragma unroll
    for (int kx = 0; kx < 3; ++kx)
        #pragma unroll
        for (int j = 0; j < XS; ++j) {
            accA[j] = fmaf(v[j + kx], wA[kx], accA[j]);
            accB[j] = fmaf(v[j + kx], wB[kx], accB[j]);
        }
}

// ---------------------------------------------------------------------------
// Main conv kernel. Grid: (W/TX=8, HP/TY=8, B*NPART=64). Block: 256 threads.
// ---------------------------------------------------------------------------
extern __shared__ float smem[];

__global__ void __launch_bounds__(NTHREADS, 4)
conv_kernel(const float* __restrict__ x,
            const float* __restrict__ bias,
            const float* __restrict__ alpha,
            const int*   __restrict__ widths,
            float* __restrict__ out)
{
    const int tile_x = blockIdx.x;
    const int tile_y = blockIdx.y;
    const int slab   = blockIdx.z;
    const int b      = slab >> 3;
    const int part   = slab & 7;
    const int width  = widths[part];
    const int x0     = tile_x * TX;
    const int y0     = tile_y * TY;          // local row in slab
    const int gy0    = part * HP_ + y0;      // global row

    const int t    = threadIdx.x;
    const int xsub = t & 7;
    const int cop  = (t >> 3) & 15;
    const int band = t >> 7;                 // 0 or 1
    const int co0  = cop * 2;
    const int xoff = xsub * XS;
    const int r0   = band * 2;               // first out row (local to tile)

    // ---- fast path: whole tile past the valid width -> zeros ----
    if (x0 >= width) {
        const float4 z = make_float4(0.f, 0.f, 0.f, 0.f);
        #pragma unroll
        for (int c = 0; c < 2; ++c)
            #pragma unroll
            for (int o = 0; o < 2; ++o) {
                int base = ((b * CO_ + co0 + c) * H_ + gy0 + r0 + o) * W_ + x0 + xoff;
                *(float4*)(out + base)     = z;
                *(float4*)(out + base + 4) = z;
            }
        return;
    }

    float* sIn = smem;                 // [ci][6][68]

    // ---- stage input tile (masked). Warp w stages ci in [4w, 4w+4). ----
    {
        const int warp = t >> 5;
        const int lane = t & 31;
        const int wlim = (width < W_) ? width : W_;
        const int ci0  = warp * 4;
        const float* xb = x + ((size_t)(b * CI_ + ci0) * H_ + part * HP_) * W_;
        float* sb = sIn + ci0 * (SIN_ROWS * SIN_COLS);
        #pragma unroll
        for (int rr = 0; rr < 24; ++rr) {
            const int cio = rr / 6;          // compile-time
            const int r   = rr % 6;          // compile-time
            const int ly  = y0 - 2 + r;      // local row in slab
            const float* grow = xb + (size_t)cio * H_ * W_ + ly * W_;
            float* srow = sb + (cio * SIN_ROWS + r) * SIN_COLS;
            const bool rowok = (ly >= 0) && (ly < HP_);
            int g0 = x0 - 2 + lane;
            int g1 = g0 + 32;
            float v0 = 0.f, v1 = 0.f;
            if (rowok) {
                if (g0 >= 0 && g0 < wlim) v0 = grow[g0];
                if (g1 < wlim)            v1 = grow[g1];
            }
            srow[lane]      = v0;
            srow[lane + 32] = v1;
            if (lane < 4) {
                int g2 = g0 + 64;
                float v2 = (rowok && g2 < wlim) ? grow[g2] : 0.f;
                srow[lane + 64] = v2;
            }
        }
    }
    __syncthreads();

    // acc[co][row][col]: row 0/1 of this thread's band, co0/co0+1
    float a00[XS], a01[XS], a10[XS], a11[XS];
    #pragma unroll
    for (int j = 0; j < XS; ++j) { a00[j]=0.f; a01[j]=0.f; a10[j]=0.f; a11[j]=0.f; }

    // Thread reads smem rows r0 .. r0+3 (out row oy uses rows oy, oy+1, oy+2)
    const float* rbase = sIn + r0 * SIN_COLS + xoff;

    #pragma unroll 1
    for (int ci = 0; ci < CI_; ++ci) {
        const float* wp = g_w + (size_t)(ci * CO_ + co0) * WROW;
        const float* rb = rbase + ci * (SIN_ROWS * SIN_COLS);

        float gA[5], gB[5], tA[5], tB[5], v[12];

        // q=0: row0 <- ky0 group
        load_g5(gA, gB, wp, 0);
        load_v(v, rb);
        fma5(a00, a10, v, gA, gB);

        // q=1: row0 <- ky1 group; row1 <- ky0 group (held)
        load_g5(tA, tB, wp, 8);
        load_v(v, rb + SIN_COLS);
        fma5(a00, a10, v, tA, tB);
        fma5(a01, a11, v, gA, gB);

        // q=2: row0 <- ky2 group; row1 <- ky1 group (held)
        load_g3(gA, gB, wp);          // reuse gA/gB[0..2]
        load_v(v, rb + 2 * SIN_COLS);
        fma3(a00, a10, v, gA, gB);
        fma5(a01, a11, v, tA, tB);

        // q=3: row1 <- ky2 group (held)
        load_v(v, rb + 3 * SIN_COLS);
        fma3(a01, a11, v, gA, gB);
    }

    // ---- epilogue: bias, leaky-ReLU, width mask, vectorized store ----
    const float* accs[2][2] = { {a00, a01}, {a10, a11} };
    #pragma unroll
    for (int c = 0; c < 2; ++c) {
        const float bz = __ldg(bias  + co0 + c);
        const float al = __ldg(alpha + co0 + c);
        #pragma unroll
        for (int o = 0; o < 2; ++o) {
            const float* ac = accs[c][o];
            float vals[XS];
            #pragma unroll
            for (int j = 0; j < XS; ++j) {
                float y = ac[j] + bz;
                y = (y > 0.f) ? y : al * y;
                int gx = x0 + xoff + j;
                vals[j] = (gx < width) ? y : 0.f;
            }
            int base = ((b * CO_ + co0 + c) * H_ + gy0 + r0 + o) * W_ + x0 + xoff;
            *(float4*)(out + base)     = make_float4(vals[0], vals[1], vals[2], vals[3]);
            *(float4*)(out + base + 4) = make_float4(vals[4], vals[5], vals[6], vals[7]);
        }
    }
}

// ---------------------------------------------------------------------------
// Launch
// ---------------------------------------------------------------------------
extern "C" void kernel_launch(void* const* d_in, const int* in_sizes, int n_in,
                              void* d_out, int out_size)
{
    const float* x      = (const float*)d_in[0];
    const float* weight = (const float*)d_in[1];
    const float* bias   = (const float*)d_in[2];
    const float* alpha  = (const float*)d_in[3];
    const int*   widths = (const int*)  d_in[4];
    float* out = (float*)d_out;

    (void)in_sizes; (void)n_in; (void)out_size;

    cudaFuncSetAttribute(conv_kernel,
                         cudaFuncAttributeMaxDynamicSharedMemorySize,
                         SMEM_BYTES);

    prep_weights<<<(CI_ * CO_ * WROW + 255) / 256, 256>>>(weight);

    dim3 grid(W_ / TX, HP_ / TY, B_ * NPART);
    conv_kernel<<<grid, NTHREADS, SMEM_BYTES>>>(x, bias, alpha, widths, out);
}

// round 8
// speedup vs baseline: 1.2058x; 1.2058x over previous
#include <cuda_runtime.h>
#include <cuda_bf16.h>

// Problem constants
#define NGROUPS 8
#define CIN 4
#define COUT 4
#define KSIZE 5
#define NPART 8
#define B_    8
#define H_    256
#define W_    512
#define CI_   32
#define CO_   32
#define HP_   32      // H_/NPART rows per slab

// Tile config: 64 cols x 4 rows x 32 co per block.
// Thread = (xsub: 8 cols) x (co-pair: 2 co) x (band: 2 rows) -> 8*16*2 = 256
#define TX 64
#define TY 4
#define XS 8
#define NTHREADS 256

#define NTAPS 13
#define SIN_ROWS 6            // TY + 2
#define SIN_COLS 68           // TX + 4
#define SIN_ELEMS (CI_ * SIN_ROWS * SIN_COLS)       // 13056
#define SMEM_BYTES (SIN_ELEMS * 4)                  // 52224 -> 3 blocks/SM

// Masked-weight scratch in global: layout [ci][co][16] (taps padded 13->16)
#define WROW 16
__device__ float g_w[CI_ * CO_ * WROW];

// ---------------------------------------------------------------------------
// Prep: apply PixelCNN group mask (HIDDEN: center visible iff gin<=gout),
// reorder weights to [ci][co][16taps].
// tap 0..9 -> ky=tap/5, kx=tap%5 ; tap 10,11 -> ky=2,kx=0,1 ; tap 12 -> center
// ---------------------------------------------------------------------------
__global__ void prep_weights(const float* __restrict__ w) {
    int i = blockIdx.x * blockDim.x + threadIdx.x;
    if (i >= CI_ * CO_ * WROW) return;
    int k  = i & 15;
    int co = (i >> 4) & 31;
    int ci = i >> 9;
    float val = 0.0f;
    if (k < NTAPS) {
        int ky, kx;
        float m = 1.0f;
        if (k < 10)      { ky = k / 5; kx = k % 5; }
        else if (k == 10){ ky = 2; kx = 0; }
        else if (k == 11){ ky = 2; kx = 1; }
        else             { ky = 2; kx = 2; m = ((ci >> 2) <= (co >> 2)) ? 1.0f : 0.0f; }
        val = w[((co * CI_ + ci) * KSIZE + ky) * KSIZE + kx] * m;
    }
    g_w[i] = val;
}

__device__ __forceinline__ void load_w(float* wgt, const float* __restrict__ wp) {
    const float4* q = (const float4*)wp;
    float4 a = __ldg(q);
    float4 b = __ldg(q + 1);
    float4 c = __ldg(q + 2);
    wgt[0]=a.x; wgt[1]=a.y; wgt[2]=a.z;  wgt[3]=a.w;
    wgt[4]=b.x; wgt[5]=b.y; wgt[6]=b.z;  wgt[7]=b.w;
    wgt[8]=c.x; wgt[9]=c.y; wgt[10]=c.z; wgt[11]=c.w;
    wgt[12] = __ldg(wp + 12);
}

// ---------------------------------------------------------------------------
// Main conv kernel. Grid: (W/TX=8, HP/TY=8, B*NPART=64). Block: 256 threads.
// ---------------------------------------------------------------------------
extern __shared__ float smem[];

__global__ void __launch_bounds__(NTHREADS, 3)
conv_kernel(const float* __restrict__ x,
            const float* __restrict__ bias,
            const float* __restrict__ alpha,
            const int*   __restrict__ widths,
            float* __restrict__ out)
{
    const int tile_x = blockIdx.x;
    const int tile_y = blockIdx.y;
    const int slab   = blockIdx.z;
    const int b      = slab >> 3;
    const int part   = slab & 7;
    const int width  = widths[part];
    const int x0     = tile_x * TX;
    const int y0     = tile_y * TY;          // local row in slab
    const int gy0    = part * HP_ + y0;      // global row

    const int t    = threadIdx.x;
    const int xsub = t & 7;
    const int cop  = (t >> 3) & 15;
    const int band = t >> 7;                 // 0 or 1
    const int co0  = cop * 2;
    const int xoff = xsub * XS;
    const int r0   = band * 2;               // first out row (local to tile)

    // ---- fast path: whole tile past the valid width -> zeros ----
    if (x0 >= width) {
        const float4 z = make_float4(0.f, 0.f, 0.f, 0.f);
        #pragma unroll
        for (int c = 0; c < 2; ++c)
            #pragma unroll
            for (int o = 0; o < 2; ++o) {
                int base = ((b * CO_ + co0 + c) * H_ + gy0 + r0 + o) * W_ + x0 + xoff;
                *(float4*)(out + base)     = z;
                *(float4*)(out + base + 4) = z;
            }
        return;
    }

    float* sIn = smem;                 // [ci][6][68]

    // ---- stage input tile (masked). Warp w stages ci in [4w, 4w+4). ----
    {
        const int warp = t >> 5;
        const int lane = t & 31;
        const int wlim = (width < W_) ? width : W_;
        const int ci0  = warp * 4;
        const float* xb = x + ((size_t)(b * CI_ + ci0) * H_ + part * HP_) * W_;
        float* sb = sIn + ci0 * (SIN_ROWS * SIN_COLS);
        #pragma unroll
        for (int rr = 0; rr < 24; ++rr) {
            const int cio = rr / 6;          // compile-time
            const int r   = rr % 6;          // compile-time
            const int ly  = y0 - 2 + r;      // local row in slab
            const float* grow = xb + (size_t)cio * H_ * W_ + ly * W_;
            float* srow = sb + (cio * SIN_ROWS + r) * SIN_COLS;
            const bool rowok = (ly >= 0) && (ly < HP_);
            int g0 = x0 - 2 + lane;
            int g1 = g0 + 32;
            float v0 = 0.f, v1 = 0.f;
            if (rowok) {
                if (g0 >= 0 && g0 < wlim) v0 = grow[g0];
                if (g1 < wlim)            v1 = grow[g1];
            }
            srow[lane]      = v0;
            srow[lane + 32] = v1;
            if (lane < 4) {
                int g2 = g0 + 64;
                float v2 = (rowok && g2 < wlim) ? grow[g2] : 0.f;
                srow[lane + 64] = v2;
            }
        }
    }
    __syncthreads();

    // acc[co][row][col]
    float acc[2][2][XS];
    #pragma unroll
    for (int c = 0; c < 2; ++c)
        #pragma unroll
        for (int o = 0; o < 2; ++o)
            #pragma unroll
            for (int j = 0; j < XS; ++j) acc[c][o][j] = 0.f;

    // Thread reads smem rows r0 .. r0+3 (out row oy uses rows oy, oy+1, oy+2)
    const float* rbase = sIn + r0 * SIN_COLS + xoff;

    // Unroll by 2 so loop-head LDG/LDS of ci+1 overlap the FMA tail of ci.
    #pragma unroll 2
    for (int ci = 0; ci < CI_; ++ci) {
        float w0[NTAPS], w1[NTAPS];
        const float* wp = g_w + (ci * CO_ + co0) * WROW;
        load_w(w0, wp);
        load_w(w1, wp + WROW);

        const float* rb = rbase + ci * (SIN_ROWS * SIN_COLS);
        #pragma unroll
        for (int q = 0; q < 4; ++q) {
            float v[12];
            const float4 a0 = *(const float4*)(rb + q * SIN_COLS);
            const float4 a1 = *(const float4*)(rb + q * SIN_COLS + 4);
            const float4 a2 = *(const float4*)(rb + q * SIN_COLS + 8);
            v[0]=a0.x; v[1]=a0.y; v[2]=a0.z; v[3]=a0.w;
            v[4]=a1.x; v[5]=a1.y; v[6]=a1.z; v[7]=a1.w;
            v[8]=a2.x; v[9]=a2.y; v[10]=a2.z; v[11]=a2.w;

            // out row 0 (local r0): ky = q, valid for q = 0,1,2
            if (q < 3) {
                const int nkx = (q == 2) ? 3 : 5;
                const int wb  = 5 * q;          // ky0->0, ky1->5, ky2->10
                #pragma unroll
                for (int kx = 0; kx < 5; ++kx) {
                    if (kx < nkx) {
                        #pragma unroll
                        for (int j = 0; j < XS; ++j) {
                            acc[0][0][j] = fmaf(v[j + kx], w0[wb + kx], acc[0][0][j]);
                            acc[1][0][j] = fmaf(v[j + kx], w1[wb + kx], acc[1][0][j]);
                        }
                    }
                }
            }
            // out row 1 (local r0+1): ky = q-1, valid for q = 1,2,3
            if (q >= 1) {
                const int ky  = q - 1;
                const int nkx = (ky == 2) ? 3 : 5;
                const int wb  = 5 * ky;
                #pragma unroll
                for (int kx = 0; kx < 5; ++kx) {
                    if (kx < nkx) {
                        #pragma unroll
                        for (int j = 0; j < XS; ++j) {
                            acc[0][1][j] = fmaf(v[j + kx], w0[wb + kx], acc[0][1][j]);
                            acc[1][1][j] = fmaf(v[j + kx], w1[wb + kx], acc[1][1][j]);
                        }
                    }
                }
            }
        }
    }

    // ---- epilogue: bias, leaky-ReLU, width mask, vectorized store ----
    #pragma unroll
    for (int c = 0; c < 2; ++c) {
        const float bz = __ldg(bias  + co0 + c);
        const float al = __ldg(alpha + co0 + c);
        #pragma unroll
        for (int o = 0; o < 2; ++o) {
            float vals[XS];
            #pragma unroll
            for (int j = 0; j < XS; ++j) {
                float y = acc[c][o][j] + bz;
                y = (y > 0.f) ? y : al * y;
                int gx = x0 + xoff + j;
                vals[j] = (gx < width) ? y : 0.f;
            }
            int base = ((b * CO_ + co0 + c) * H_ + gy0 + r0 + o) * W_ + x0 + xoff;
            *(float4*)(out + base)     = make_float4(vals[0], vals[1], vals[2], vals[3]);
            *(float4*)(out + base + 4) = make_float4(vals[4], vals[5], vals[6], vals[7]);
        }
    }
}

// ---------------------------------------------------------------------------
// Launch
// ---------------------------------------------------------------------------
extern "C" void kernel_launch(void* const* d_in, const int* in_sizes, int n_in,
                              void* d_out, int out_size)
{
    const float* x      = (const float*)d_in[0];
    const float* weight = (const float*)d_in[1];
    const float* bias   = (const float*)d_in[2];
    const float* alpha  = (const float*)d_in[3];
    const int*   widths = (const int*)  d_in[4];
    float* out = (float*)d_out;

    (void)in_sizes; (void)n_in; (void)out_size;

    cudaFuncSetAttribute(conv_kernel,
                         cudaFuncAttributeMaxDynamicSharedMemorySize,
                         SMEM_BYTES);

    prep_weights<<<(CI_ * CO_ * WROW + 255) / 256, 256>>>(weight);

    dim3 grid(W_ / TX, HP_ / TY, B_ * NPART);
    conv_kernel<<<grid, NTHREADS, SMEM_BYTES>>>(x, bias, alpha, widths, out);
}